// round 1
// baseline (speedup 1.0000x reference)
#include <cuda_runtime.h>

#define NNODES 100000
#define NEDGES 1600000
#define F 128
#define SCAN_T 1024
#define NSCAN ((NNODES + SCAN_T - 1) / SCAN_T)   // 98

// ---------------- scratch (static __device__, no allocs) ----------------
__device__ int   g_deg[NNODES];
__device__ float g_invdeg[NNODES];
__device__ int   g_rowptr[NNODES + 1];
__device__ int   g_cursor[NNODES];
__device__ int   g_csrsrc[NEDGES];
__device__ int   g_partials[NSCAN];
__device__ int   g_scanbuf[NNODES];
__device__ float g_h0[NNODES * F];
__device__ float g_h1[NNODES * F];
__device__ float g_mean[NNODES * F];
__device__ float g_A[NNODES * F];
__device__ float g_B[NNODES * F];

// ---------------- CSR build ----------------
__global__ void k_zero_deg() {
    int i = blockIdx.x * blockDim.x + threadIdx.x;
    if (i < NNODES) g_deg[i] = 0;
}

__global__ void k_hist(const int* __restrict__ dst) {
    int e = blockIdx.x * blockDim.x + threadIdx.x;
    if (e < NEDGES) atomicAdd(&g_deg[dst[e]], 1);
}

__global__ void k_scan1() {
    __shared__ int sd[SCAN_T];
    int t = threadIdx.x;
    int i = blockIdx.x * SCAN_T + t;
    int v = (i < NNODES) ? g_deg[i] : 0;
    sd[t] = v;
    __syncthreads();
    for (int off = 1; off < SCAN_T; off <<= 1) {
        int add = (t >= off) ? sd[t - off] : 0;
        __syncthreads();
        sd[t] += add;
        __syncthreads();
    }
    if (i < NNODES) g_scanbuf[i] = sd[t];
    if (t == SCAN_T - 1) g_partials[blockIdx.x] = sd[t];
}

__global__ void k_scan2() {
    if (threadIdx.x == 0) {
        int run = 0;
        for (int b = 0; b < NSCAN; b++) {
            int p = g_partials[b];
            g_partials[b] = run;
            run += p;
        }
    }
}

__global__ void k_scan3() {
    int i = blockIdx.x * blockDim.x + threadIdx.x;
    if (i < NNODES) {
        int incl = g_scanbuf[i] + g_partials[i >> 10];
        int d = g_deg[i];
        int excl = incl - d;
        g_rowptr[i] = excl;
        g_cursor[i] = excl;
        g_invdeg[i] = 1.0f / fmaxf((float)d, 1.0f);
        if (i == 0) g_rowptr[NNODES] = NEDGES;
    }
}

__global__ void k_scatter(const int* __restrict__ src, const int* __restrict__ dst) {
    int e = blockIdx.x * blockDim.x + threadIdx.x;
    if (e < NEDGES) {
        int pos = atomicAdd(&g_cursor[dst[e]], 1);
        g_csrsrc[pos] = src[e];
    }
}

// ---------------- mean aggregation (one warp per dst node) ----------------
__global__ void __launch_bounds__(256) k_aggmean(const float* __restrict__ h) {
    int w    = (blockIdx.x * blockDim.x + threadIdx.x) >> 5;
    int lane = threadIdx.x & 31;
    if (w >= NNODES) return;
    int beg = g_rowptr[w], end = g_rowptr[w + 1];
    int f0 = lane * 4;
    float4 acc = make_float4(0.f, 0.f, 0.f, 0.f);
    for (int i = beg; i < end; i += 32) {
        int n = min(32, end - i);
        int sidx = (lane < n) ? g_csrsrc[i + lane] : 0;
        for (int j = 0; j < n; j++) {
            int s = __shfl_sync(0xffffffffu, sidx, j);
            const float4 v = *reinterpret_cast<const float4*>(h + s * F + f0);
            acc.x += v.x; acc.y += v.y; acc.z += v.z; acc.w += v.w;
        }
    }
    float sc = g_invdeg[w];
    acc.x *= sc; acc.y *= sc; acc.z *= sc; acc.w *= sc;
    *reinterpret_cast<float4*>(g_mean + w * F + f0) = acc;
}

// ---------------- fused GEMM: out = X1@W1 (+ g_mean@W2) (+bias) (+leaky) ----------------
// M x 128 @ 128 x 128, BM=128 BN=128 BK=16, 256 threads, TM=TN=8
template <bool HAS2, bool LEAKY>
__global__ void __launch_bounds__(256) gemm128(
    const float* __restrict__ X1, const float* __restrict__ W1,
    const float* __restrict__ W2, const float* __restrict__ bias,
    float* __restrict__ out, int M)
{
    __shared__ float As1[16][128];
    __shared__ float As2[16][128];
    __shared__ float Ws1[16][128];
    __shared__ float Ws2[16][128];

    const int tid = threadIdx.x;
    const int tr = tid >> 4;      // 0..15 (row group)
    const int tc = tid & 15;      // 0..15 (col group)
    const int rowBase = blockIdx.x * 128;

    float acc[8][8];
#pragma unroll
    for (int i = 0; i < 8; i++)
#pragma unroll
        for (int j = 0; j < 8; j++) acc[i][j] = 0.f;

    for (int k0 = 0; k0 < 128; k0 += 16) {
#pragma unroll
        for (int q = 0; q < 2; q++) {
            int idx = tid * 2 + q;            // 0..511
            // A tiles: r = row in block, kc = k sub-offset
            int r  = idx >> 2;
            int kc = (idx & 3) * 4;
            int grow = rowBase + r;
            float4 v1 = make_float4(0.f, 0.f, 0.f, 0.f);
            float4 v2 = make_float4(0.f, 0.f, 0.f, 0.f);
            if (grow < M) {
                v1 = *reinterpret_cast<const float4*>(X1 + grow * F + k0 + kc);
                if (HAS2)
                    v2 = *reinterpret_cast<const float4*>(g_mean + grow * F + k0 + kc);
            }
            As1[kc + 0][r] = v1.x; As1[kc + 1][r] = v1.y;
            As1[kc + 2][r] = v1.z; As1[kc + 3][r] = v1.w;
            if (HAS2) {
                As2[kc + 0][r] = v2.x; As2[kc + 1][r] = v2.y;
                As2[kc + 2][r] = v2.z; As2[kc + 3][r] = v2.w;
            }
            // W tiles
            int kk = idx >> 5;
            int c  = (idx & 31) * 4;
            *reinterpret_cast<float4*>(&Ws1[kk][c]) =
                *reinterpret_cast<const float4*>(W1 + (k0 + kk) * F + c);
            if (HAS2)
                *reinterpret_cast<float4*>(&Ws2[kk][c]) =
                    *reinterpret_cast<const float4*>(W2 + (k0 + kk) * F + c);
        }
        __syncthreads();

#pragma unroll
        for (int kk = 0; kk < 16; kk++) {
            float a1[8], w1[8];
            *reinterpret_cast<float4*>(&a1[0]) = *reinterpret_cast<const float4*>(&As1[kk][tr * 8]);
            *reinterpret_cast<float4*>(&a1[4]) = *reinterpret_cast<const float4*>(&As1[kk][tr * 8 + 4]);
            *reinterpret_cast<float4*>(&w1[0]) = *reinterpret_cast<const float4*>(&Ws1[kk][tc * 8]);
            *reinterpret_cast<float4*>(&w1[4]) = *reinterpret_cast<const float4*>(&Ws1[kk][tc * 8 + 4]);
#pragma unroll
            for (int i = 0; i < 8; i++)
#pragma unroll
                for (int j = 0; j < 8; j++) acc[i][j] = fmaf(a1[i], w1[j], acc[i][j]);
            if (HAS2) {
                float a2[8], w2[8];
                *reinterpret_cast<float4*>(&a2[0]) = *reinterpret_cast<const float4*>(&As2[kk][tr * 8]);
                *reinterpret_cast<float4*>(&a2[4]) = *reinterpret_cast<const float4*>(&As2[kk][tr * 8 + 4]);
                *reinterpret_cast<float4*>(&w2[0]) = *reinterpret_cast<const float4*>(&Ws2[kk][tc * 8]);
                *reinterpret_cast<float4*>(&w2[4]) = *reinterpret_cast<const float4*>(&Ws2[kk][tc * 8 + 4]);
#pragma unroll
                for (int i = 0; i < 8; i++)
#pragma unroll
                    for (int j = 0; j < 8; j++) acc[i][j] = fmaf(a2[i], w2[j], acc[i][j]);
            }
        }
        __syncthreads();
    }

    // epilogue
    float bv[8];
#pragma unroll
    for (int j = 0; j < 8; j++) bv[j] = bias ? bias[tc * 8 + j] : 0.f;

#pragma unroll
    for (int i = 0; i < 8; i++) {
        int grow = rowBase + tr * 8 + i;
        if (grow < M) {
            float o[8];
#pragma unroll
            for (int j = 0; j < 8; j++) {
                float v = acc[i][j] + bv[j];
                if (LEAKY) v = (v > 0.f) ? v : 0.01f * v;
                o[j] = v;
            }
            float* dst = out + grow * F + tc * 8;
            *reinterpret_cast<float4*>(dst)     = *reinterpret_cast<float4*>(&o[0]);
            *reinterpret_cast<float4*>(dst + 4) = *reinterpret_cast<float4*>(&o[4]);
        }
    }
}

// ---------------- edge MLP (one warp per edge) ----------------
__global__ void __launch_bounds__(256) k_edge(
    const int* __restrict__ src, const int* __restrict__ dst,
    const float* __restrict__ efeat, const float* __restrict__ mw1,
    const float* __restrict__ mw2, const float* __restrict__ mb2,
    float* __restrict__ out)
{
    int w    = (blockIdx.x * blockDim.x + threadIdx.x) >> 5;
    int lane = threadIdx.x & 31;
    if (w >= NEDGES) return;
    int s = src[w], d = dst[w];
    float e = efeat[w];
    int f0 = lane * 4;

    float4 a  = *reinterpret_cast<const float4*>(g_A + s * F + f0);
    float4 b  = *reinterpret_cast<const float4*>(g_B + d * F + f0);
    float4 wr = *reinterpret_cast<const float4*>(mw1 + 256 * F + f0);

    float4 hv;
    hv.x = fmaxf(fmaf(e, wr.x, a.x + b.x), 0.f);
    hv.y = fmaxf(fmaf(e, wr.y, a.y + b.y), 0.f);
    hv.z = fmaxf(fmaf(e, wr.z, a.z + b.z), 0.f);
    hv.w = fmaxf(fmaf(e, wr.w, a.w + b.w), 0.f);

    // mw2 is [128][2]
    float4 q0 = *reinterpret_cast<const float4*>(mw2 + f0 * 2);
    float4 q1 = *reinterpret_cast<const float4*>(mw2 + f0 * 2 + 4);
    float p0 = hv.x * q0.x + hv.y * q0.z + hv.z * q1.x + hv.w * q1.z;
    float p1 = hv.x * q0.y + hv.y * q0.w + hv.z * q1.y + hv.w * q1.w;

#pragma unroll
    for (int off = 16; off; off >>= 1) {
        p0 += __shfl_xor_sync(0xffffffffu, p0, off);
        p1 += __shfl_xor_sync(0xffffffffu, p1, off);
    }
    if (lane == 0) {
        out[2 * w]     = p0 + mb2[0];
        out[2 * w + 1] = p1 + mb2[1];
    }
}

// ---------------- launch ----------------
extern "C" void kernel_launch(void* const* d_in, const int* in_sizes, int n_in,
                              void* d_out, int out_size) {
    const float* node = (const float*)d_in[0];
    const float* ef   = (const float*)d_in[1];
    const int*   src  = (const int*)d_in[2];
    const int*   dst  = (const int*)d_in[3];
    const float* ws0 = (const float*)d_in[4];
    const float* wn0 = (const float*)d_in[5];
    const float* b0  = (const float*)d_in[6];
    const float* ws1 = (const float*)d_in[7];
    const float* wn1 = (const float*)d_in[8];
    const float* b1  = (const float*)d_in[9];
    const float* ws2 = (const float*)d_in[10];
    const float* wn2 = (const float*)d_in[11];
    const float* b2  = (const float*)d_in[12];
    const float* mw1 = (const float*)d_in[13];
    const float* mb1 = (const float*)d_in[14];
    const float* mw2 = (const float*)d_in[15];
    const float* mb2 = (const float*)d_in[16];
    float* out = (float*)d_out;

    float *h0, *h1, *pA, *pB;
    cudaGetSymbolAddress((void**)&h0, g_h0);
    cudaGetSymbolAddress((void**)&h1, g_h1);
    cudaGetSymbolAddress((void**)&pA, g_A);
    cudaGetSymbolAddress((void**)&pB, g_B);

    // CSR build (once, reused for all 3 layers)
    k_zero_deg<<<(NNODES + 255) / 256, 256>>>();
    k_hist<<<(NEDGES + 255) / 256, 256>>>(dst);
    k_scan1<<<NSCAN, SCAN_T>>>();
    k_scan2<<<1, 32>>>();
    k_scan3<<<(NNODES + 255) / 256, 256>>>();
    k_scatter<<<(NEDGES + 255) / 256, 256>>>(src, dst);

    const int aggBlocks  = (NNODES * 32 + 255) / 256;
    const int gemmBlocks = (NNODES + 127) / 128;
    const int edgeBlocks = (NEDGES * 32 + 255) / 256 ;

    // layer 0: node_feats -> h0
    k_aggmean<<<aggBlocks, 256>>>(node);
    gemm128<true, true><<<gemmBlocks, 256>>>(node, ws0, wn0, b0, h0, NNODES);
    // layer 1: h0 -> h1
    k_aggmean<<<aggBlocks, 256>>>(h0);
    gemm128<true, true><<<gemmBlocks, 256>>>(h0, ws1, wn1, b1, h1, NNODES);
    // layer 2: h1 -> h0
    k_aggmean<<<aggBlocks, 256>>>(h1);
    gemm128<true, true><<<gemmBlocks, 256>>>(h1, ws2, wn2, b2, h0, NNODES);

    // node-level precompute of the factored edge MLP:
    // A = h @ mw1[0:128]   + mb1 ;  B = h @ mw1[128:256]
    gemm128<false, false><<<gemmBlocks, 256>>>(h0, mw1, nullptr, mb1, pA, NNODES);
    gemm128<false, false><<<gemmBlocks, 256>>>(h0, mw1 + 128 * F, nullptr, nullptr, pB, NNODES);

    // edge MLP
    k_edge<<<edgeBlocks, 256>>>(src, dst, ef, mw1, mw2, mb2, out);
}